// round 1
// baseline (speedup 1.0000x reference)
#include <cuda_runtime.h>

// Problem constants (fixed shapes per metadata):
//   d_in[0] = x            float32 [65536*64]
//   d_in[1] = edge_index   int32   [2*262144]  (src = first E, dst = next E)
//   d_in[2] = edge_attr    float32 [262144]
//   d_in[3] = pathway      int32   [128*512]
//   d_in[4] = batch        int32   [65536]
//   d_out   = pooled       float32 [16*64]

#define NN   65536
#define BB   16
#define EE   262144
#define PTOT 128
#define LL   512
#define PPER 8
#define FF   64

// Scratch (no allocation allowed -> __device__ globals)
__device__ unsigned int g_mask[NN];
__device__ int          g_counts[BB];
__device__ int          g_start[BB + 1];
__device__ float        g_w[EE];
__device__ float        g_x0[NN * FF];
__device__ float        g_x1[NN * FF];
__device__ float        g_pool[BB * FF];

__global__ void k_zero() {
    int i = blockIdx.x * blockDim.x + threadIdx.x;
    if (i < NN) g_mask[i] = 0u;
    if (i < BB) g_counts[i] = 0;
    if (i < BB * FF) g_pool[i] = 0.f;
}

__global__ void k_count(const int* __restrict__ batch) {
    __shared__ int sh[BB];
    if (threadIdx.x < BB) sh[threadIdx.x] = 0;
    __syncthreads();
    int i = blockIdx.x * blockDim.x + threadIdx.x;
    if (i < NN) atomicAdd(&sh[batch[i]], 1);
    __syncthreads();
    if (threadIdx.x < BB) atomicAdd(&g_counts[threadIdx.x], sh[threadIdx.x]);
}

__global__ void k_start() {
    int acc = 0;
    for (int g = 0; g < BB; g++) { g_start[g] = acc; acc += g_counts[g]; }
    g_start[BB] = acc;
}

// Build 8-bit pathway-membership mask per node.
// Pathway p belongs to graph p/PPER; ids are graph-local -> shift by node_start.
__global__ void k_mask(const int* __restrict__ pw) {
    int i = blockIdx.x * blockDim.x + threadIdx.x;
    if (i >= PTOT * LL) return;
    int p  = i / LL;
    int id = pw[i];
    if (id >= 0) {
        int n = id + g_start[p / PPER];
        atomicOr(&g_mask[n], 1u << (p % PPER));
    }
}

// w[e] = edge_attr[e] * popcount(mask[src] & mask[dst]) for same-graph edges.
__global__ void k_w(const int* __restrict__ src, const int* __restrict__ dst,
                    const float* __restrict__ attr, const int* __restrict__ batch) {
    int e = blockIdx.x * blockDim.x + threadIdx.x;
    if (e >= EE) return;
    int s = src[e], d = dst[e];
    unsigned m = g_mask[s] & g_mask[d];
    float c = (batch[s] == batch[d]) ? (float)__popc(m) : 0.f;
    g_w[e] = c * attr[e];
}

// y = node_count * x  (elementwise, float4)
__global__ void __launch_bounds__(256)
k_init(const float4* __restrict__ xin, float4* __restrict__ yout) {
    int i = blockIdx.x * blockDim.x + threadIdx.x;
    if (i >= NN * (FF / 4)) return;
    int n = i >> 4;  // i / (FF/4)
    float nc = (float)__popc(g_mask[n]);
    float4 v = xin[i];
    v.x *= nc; v.y *= nc; v.z *= nc; v.w *= nc;
    yout[i] = v;
}

// y[dst] += w[e] * x[src]  — ~99% of edges have w==0 (early exit).
__global__ void __launch_bounds__(256)
k_edge(const int* __restrict__ src, const int* __restrict__ dst,
       const float* __restrict__ xin, float* __restrict__ yout) {
    int e = blockIdx.x * blockDim.x + threadIdx.x;
    if (e >= EE) return;
    float wv = g_w[e];
    if (wv == 0.f) return;
    int s = src[e] * FF, d = dst[e] * FF;
    #pragma unroll
    for (int c = 0; c < FF; c += 4) {
        float4 v = *reinterpret_cast<const float4*>(xin + s + c);
        atomicAdd(yout + d + c + 0, v.x * wv);
        atomicAdd(yout + d + c + 1, v.y * wv);
        atomicAdd(yout + d + c + 2, v.z * wv);
        atomicAdd(yout + d + c + 3, v.w * wv);
    }
}

// Per-graph feature sums. grid = BB*CHUNKS blocks of 1024 threads.
// Relies on batch being sorted (node_start ranges), as the reference's
// cumsum-shift logic does.
#define PCHUNKS 8
__global__ void __launch_bounds__(1024)
k_pool(const float* __restrict__ x) {
    int g = blockIdx.x / PCHUNKS, chunk = blockIdx.x % PCHUNKS;
    int s = g_start[g], e = g_start[g + 1];
    long long cnt = e - s;
    int c0 = s + (int)((cnt * chunk) / PCHUNKS);
    int c1 = s + (int)((cnt * (chunk + 1)) / PCHUNKS);
    int f   = threadIdx.x & (FF - 1);
    int sub = threadIdx.x >> 6;  // 0..15
    float acc = 0.f;
    for (int n = c0 + sub; n < c1; n += 16)
        acc += x[n * FF + f];
    __shared__ float sh[1024];
    sh[threadIdx.x] = acc;
    __syncthreads();
    if (sub < 8) sh[threadIdx.x] += sh[threadIdx.x + 512];
    __syncthreads();
    if (sub < 4) sh[threadIdx.x] += sh[threadIdx.x + 256];
    __syncthreads();
    if (sub < 2) sh[threadIdx.x] += sh[threadIdx.x + 128];
    __syncthreads();
    if (sub == 0) {
        float v = sh[threadIdx.x] + sh[threadIdx.x + 64];
        atomicAdd(&g_pool[g * FF + f], v);
    }
}

__global__ void k_final(float* __restrict__ out) {
    int i = blockIdx.x * blockDim.x + threadIdx.x;
    if (i < BB * FF) {
        int g = i / FF;
        out[i] = g_pool[i] / (float)g_counts[g];
    }
}

extern "C" void kernel_launch(void* const* d_in, const int* in_sizes, int n_in,
                              void* d_out, int out_size) {
    const float* x     = (const float*)d_in[0];
    const int*   ei    = (const int*)d_in[1];
    const float* attr  = (const float*)d_in[2];
    const int*   pw    = (const int*)d_in[3];
    const int*   batch = (const int*)d_in[4];
    const int* src = ei;
    const int* dst = ei + EE;
    float* out = (float*)d_out;

    float *px0, *px1;
    cudaGetSymbolAddress((void**)&px0, g_x0);
    cudaGetSymbolAddress((void**)&px1, g_x1);

    k_zero <<<(NN + 255) / 256, 256>>>();
    k_count<<<(NN + 255) / 256, 256>>>(batch);
    k_start<<<1, 1>>>();
    k_mask <<<(PTOT * LL + 255) / 256, 256>>>(pw);
    k_w    <<<(EE + 255) / 256, 256>>>(src, dst, attr, batch);

    const int initGrid = (NN * (FF / 4) + 255) / 256;
    const int edgeGrid = (EE + 255) / 256;

    // Layer 1: x (input) -> g_x0
    k_init<<<initGrid, 256>>>((const float4*)x, (float4*)px0);
    k_edge<<<edgeGrid, 256>>>(src, dst, x, px0);
    // Layer 2: g_x0 -> g_x1
    k_init<<<initGrid, 256>>>((const float4*)px0, (float4*)px1);
    k_edge<<<edgeGrid, 256>>>(src, dst, px0, px1);
    // Layer 3: g_x1 -> g_x0
    k_init<<<initGrid, 256>>>((const float4*)px1, (float4*)px0);
    k_edge<<<edgeGrid, 256>>>(src, dst, px1, px0);

    k_pool <<<BB * PCHUNKS, 1024>>>(px0);
    k_final<<<(BB * FF + 255) / 256, 256>>>(out);
}